// round 10
// baseline (speedup 1.0000x reference)
#include <cuda_runtime.h>
#include <cuda_bf16.h>
#include <math.h>
#include <stdint.h>

// Problem constants
#define Bn   32
#define DQ   512
#define DK   512
#define NK   16
#define Hn   8
#define Tt   12
#define Nn   207
#define Cc   64
#define TNC  (Tt*Nn*Cc)      // 158976
#define Mrows (Bn*NK)        // 512
#define Ncols (Hn*DQ)        // 4096
#define NXB  32              // GEMM col blocks (4096/128)
#define NYB  4               // GEMM row blocks (512/128)
#define NGEMM (NXB*NYB)      // 128 GEMM blocks
#define NPF  256             // prefetch blocks
#define PB   9               // prefetched V batches (91.6 MB < L2 126MB)
#define PF_F4 ((size_t)PB * TNC * NK / 4)   // 5,723,136 float4

__device__ float g_part[NXB * Mrows];  // per-colblock logits partials
__device__ float g_att[Mrows];         // softmax weights
__device__ unsigned g_cnt = 0;         // completion counter (wraps mod NGEMM)
__device__ float g_dummy;              // prefetch sink (never actually written)

// V-batch schedule: P batches (0..8, L2-resident) interleaved ~1:2.5 among
// streaming batches so DRAM streams continuously while L2 serves P rows.
__constant__ int c_perm[Bn] = {
    9,10, 0,11,12,13, 1,14,15, 2,16,17,18, 3,19,20,
    4,21,22,23, 5,24,25,26, 6,27,28, 7,29,30, 8,31
};

// ---------------------------------------------------------------------------
__device__ __forceinline__ void mma_tf32(float* c, const uint32_t* a,
                                         uint32_t b0, uint32_t b1) {
    asm volatile(
        "mma.sync.aligned.m16n8k8.row.col.f32.tf32.tf32.f32 "
        "{%0,%1,%2,%3}, {%4,%5,%6,%7}, {%8,%9}, {%0,%1,%2,%3};"
        : "+f"(c[0]), "+f"(c[1]), "+f"(c[2]), "+f"(c[3])
        : "r"(a[0]), "r"(a[1]), "r"(a[2]), "r"(a[3]), "r"(b0), "r"(b1));
}

__device__ __forceinline__ void cp_async16(uint32_t smem_addr, const void* gptr) {
    asm volatile("cp.async.cg.shared.global [%0], [%1], 16;"
                 :: "r"(smem_addr), "l"(gptr));
}

// ---------------------------------------------------------------------------
// Kernel A (fused): blocks [0,128) = tf32 GEMM (R5-proven config) + last-block
// softmax; blocks [128,384) = V prefetch into L2 (__ldcg) of batches 0..PB-1.
// GEMM: BM=128,BN=128,BK=32; 256 thr (2x4 warps), warp tile 64x32; 2-stage
// cp.async; A direct from keys (fused transpose, XOR-swizzled).
// ---------------------------------------------------------------------------
#define SSTR 36
#define A_TILE_F 4096
#define B_TILE_F (128 * SSTR)
#define GEMM_SMEM_F (2*(A_TILE_F + B_TILE_F) + 8*128 + 128 + 128 + 512)
#define GEMM_SMEM_BYTES (GEMM_SMEM_F * 4)

__global__ __launch_bounds__(256, 2)
void gemm_att_pf(const float* __restrict__ keys, const float* __restrict__ W,
                 const float* __restrict__ bias, const float* __restrict__ query,
                 const float* __restrict__ V,
                 float* __restrict__ part, float* __restrict__ att) {
    int tid = threadIdx.x;

    // ---------------- prefetch role ----------------
    if (blockIdx.x >= NGEMM) {
        size_t gid = (size_t)(blockIdx.x - NGEMM) * 256 + tid;
        const float4* v4 = (const float4*)V;
        float s = 0.0f;
        for (size_t i = gid; i < PF_F4; i += (size_t)NPF * 256) {
            float4 p = __ldcg(v4 + i);       // fill L2, skip L1
            s += p.x + p.y + p.z + p.w;
        }
        if (s == 1.702e38f) g_dummy = s;     // unprovable-dead sink
        return;
    }

    // ---------------- GEMM role ----------------
    extern __shared__ float smem[];
    float* As    = smem;                      // 2 * 4096 [bloc*512 + d*16 + k] swz
    float* Bs    = As + 2 * A_TILE_F;         // 2 * 4608 [n*36 + d]
    float* Qs    = Bs + 2 * B_TILE_F;         // 8*128
    float* biasS = Qs + 8 * 128;              // 128
    float* partS = biasS + 128;               // 128
    float* redS  = partS + 128;               // 512

    int lane = tid & 31;
    int warp = tid >> 5;
    int warp_m = warp >> 2;        // 0..1
    int warp_n = warp & 3;         // 0..3
    int g   = lane >> 2;           // 0..7
    int tig = lane & 3;            // 0..3
    int swz = (tig & 2) << 2;

    int bx = blockIdx.x & (NXB - 1);
    int by = blockIdx.x >> 5;
    int c0 = bx * 128;
    int m0 = by * 128;
    int q0 = c0 & (DQ - 1);
    int b0 = m0 >> 4;              // 8 batches per 128 rows

    uint32_t sA = (uint32_t)__cvta_generic_to_shared(As);
    uint32_t sB = (uint32_t)__cvta_generic_to_shared(Bs);

    for (int i = tid; i < 8 * 128; i += 256)
        Qs[i] = query[(b0 + (i >> 7)) * DQ + q0 + (i & 127)];
    if (tid < 128) { biasS[tid] = bias[c0 + tid]; partS[tid] = 0.0f; }

    auto issue_tile = [&](int kt, int s) {
        uint32_t aBase = sA + (uint32_t)(s * A_TILE_F) * 4;
        uint32_t bBase = sB + (uint32_t)(s * B_TILE_F) * 4;
        #pragma unroll
        for (int i = 0; i < 2; i++) {
            int flat = i * 256 + tid;          // 0..511
            int bloc = flat >> 7;              // 0..3 -> but 8 blocs: flat covers 512 of 1024
            int rem  = flat & 127;
            int dl   = rem >> 2;               // 0..31
            int kkc  = rem & 3;                // 0..3
            // two passes over bloc: i selects bloc group via flat>>7 (0..3),
            // second half of blocs handled below
            const float* src = keys + (size_t)(b0 + bloc) * (DK * NK)
                             + (size_t)(kt + dl) * NK + kkc * 4;
            int woff = bloc * 512 + dl * 16 + ((kkc * 4) ^ ((dl & 2) << 2));
            cp_async16(aBase + (uint32_t)woff * 4, src);
        }
        #pragma unroll
        for (int i = 0; i < 2; i++) {
            int flat = i * 256 + tid;
            int bloc = 4 + (flat >> 7);        // 4..7
            int rem  = flat & 127;
            int dl   = rem >> 2;
            int kkc  = rem & 3;
            const float* src = keys + (size_t)(b0 + bloc) * (DK * NK)
                             + (size_t)(kt + dl) * NK + kkc * 4;
            int woff = bloc * 512 + dl * 16 + ((kkc * 4) ^ ((dl & 2) << 2));
            cp_async16(aBase + (uint32_t)woff * 4, src);
        }
        #pragma unroll
        for (int i = 0; i < 4; i++) {
            int flat = i * 256 + tid;
            int r = flat >> 3, cc = flat & 7;
            const float* src = W + (size_t)(c0 + r) * DK + kt + cc * 4;
            cp_async16(bBase + (uint32_t)(r * SSTR + cc * 4) * 4, src);
        }
        asm volatile("cp.async.commit_group;");
    };

    float acc[4][4][4] = {};
    issue_tile(0, 0);

    for (int it = 0; it < 16; it++) {
        int buf = it & 1;
        if (it < 15) {
            issue_tile((it + 1) * 32, buf ^ 1);
            asm volatile("cp.async.wait_group 1;");
        } else {
            asm volatile("cp.async.wait_group 0;");
        }
        __syncthreads();

        const float* Ab = As + buf * A_TILE_F;
        const float* Bb = Bs + buf * B_TILE_F;

        #pragma unroll
        for (int ks = 0; ks < 4; ks++) {
            int k = ks * 8 + tig;
            uint32_t a[4][4];
            #pragma unroll
            for (int mt = 0; mt < 4; mt++) {
                int bloc = warp_m * 4 + mt;
                const float* ab = &Ab[bloc * 512];
                a[mt][0] = __float_as_uint(ab[(k    ) * 16 + ( g      ^ swz)]);
                a[mt][1] = __float_as_uint(ab[(k    ) * 16 + ((g + 8) ^ swz)]);
                a[mt][2] = __float_as_uint(ab[(k + 4) * 16 + ( g      ^ swz)]);
                a[mt][3] = __float_as_uint(ab[(k + 4) * 16 + ((g + 8) ^ swz)]);
            }
            #pragma unroll
            for (int nt = 0; nt < 4; nt++) {
                int nbase = warp_n * 32 + nt * 8 + g;
                uint32_t b0r = __float_as_uint(Bb[nbase * SSTR + k    ]);
                uint32_t b1r = __float_as_uint(Bb[nbase * SSTR + k + 4]);
                #pragma unroll
                for (int mt = 0; mt < 4; mt++)
                    mma_tf32(acc[mt][nt], a[mt], b0r, b1r);
            }
        }
        __syncthreads();
    }

    // Epilogue: bias + relu + Q-weight, reduce per row
    #pragma unroll
    for (int mt = 0; mt < 4; mt++) {
        int mlo = warp_m * 64 + mt * 16 + g;
        int mhi = mlo + 8;
        const float* q_lo = &Qs[(mlo >> 4) * 128];
        const float* q_hi = &Qs[(mhi >> 4) * 128];
        float p_lo = 0.0f, p_hi = 0.0f;
        #pragma unroll
        for (int nt = 0; nt < 4; nt++) {
            int cl = warp_n * 32 + nt * 8 + 2 * tig;
            float bi0 = biasS[cl], bi1 = biasS[cl + 1];
            p_lo = fmaf(fmaxf(acc[mt][nt][0] + bi0, 0.0f), q_lo[cl],     p_lo);
            p_lo = fmaf(fmaxf(acc[mt][nt][1] + bi1, 0.0f), q_lo[cl + 1], p_lo);
            p_hi = fmaf(fmaxf(acc[mt][nt][2] + bi0, 0.0f), q_hi[cl],     p_hi);
            p_hi = fmaf(fmaxf(acc[mt][nt][3] + bi1, 0.0f), q_hi[cl + 1], p_hi);
        }
        p_lo += __shfl_xor_sync(0xffffffffu, p_lo, 1);
        p_lo += __shfl_xor_sync(0xffffffffu, p_lo, 2);
        p_hi += __shfl_xor_sync(0xffffffffu, p_hi, 1);
        p_hi += __shfl_xor_sync(0xffffffffu, p_hi, 2);
        if (tig == 0) {
            atomicAdd(&partS[mlo], p_lo);
            atomicAdd(&partS[mhi], p_hi);
        }
    }
    __syncthreads();
    if (tid < 128) part[bx * Mrows + m0 + tid] = partS[tid];

    // ---- last GEMM block: reduce partials + softmax ----
    __threadfence();
    __shared__ unsigned s_last;
    if (tid == 0) {
        unsigned old;
        asm volatile("atom.global.inc.u32 %0, [%1], %2;"
                     : "=r"(old) : "l"(&g_cnt), "r"((unsigned)(NGEMM - 1)) : "memory");
        s_last = (old == NGEMM - 1);
    }
    __syncthreads();
    if (!s_last) return;

    for (int m = tid; m < Mrows; m += 256) {
        float s = 0.0f;
        #pragma unroll
        for (int x = 0; x < NXB; x++) s += part[x * Mrows + m];
        redS[m] = s;
    }
    __syncthreads();
    if (tid < Bn) {
        const float scale = 1.0f / (8.0f * 22.62741699796952f);  // 1/(H*sqrt(512))
        float v[NK], mx = -1e30f;
        #pragma unroll
        for (int k = 0; k < NK; k++) { v[k] = redS[tid * NK + k] * scale; mx = fmaxf(mx, v[k]); }
        float z = 0.0f;
        #pragma unroll
        for (int k = 0; k < NK; k++) { v[k] = __expf(v[k] - mx); z += v[k]; }
        float inv = 1.0f / z;
        #pragma unroll
        for (int k = 0; k < NK; k++) att[tid * NK + k] = v[k] * inv;
    }
}

// ---------------------------------------------------------------------------
// Kernel C: att-weighted V reduction.
// Batches 0..PB-1 were prefetched into L2 -> default loads (L2 hits).
// Other batches stream with __ldcs (evict-first: preserves the resident set).
// c_perm interleaves the two classes so DRAM streams while L2 serves hits.
// ---------------------------------------------------------------------------
__global__ __launch_bounds__(256)
void weighted_v_kernel(const float* __restrict__ V, const float* __restrict__ att,
                       float* __restrict__ out) {
    __shared__ float aw[NK];
    int b = c_perm[blockIdx.y];
    if (threadIdx.x < NK) aw[threadIdx.x] = att[b * NK + threadIdx.x];
    __syncthreads();
    int i = blockIdx.x * blockDim.x + threadIdx.x;
    if (i >= TNC) return;
    const float4* v4 = (const float4*)(V + ((size_t)b * TNC + i) * NK);
    float4 p0, p1, p2, p3;
    if (b < PB) {                 // L2-resident: normal caching
        p0 = v4[0]; p1 = v4[1]; p2 = v4[2]; p3 = v4[3];
    } else {                      // streaming: evict-first
        p0 = __ldcs(v4 + 0); p1 = __ldcs(v4 + 1);
        p2 = __ldcs(v4 + 2); p3 = __ldcs(v4 + 3);
    }
    float s;
    s  = p0.x * aw[0]  + p0.y * aw[1]  + p0.z * aw[2]  + p0.w * aw[3];
    s += p1.x * aw[4]  + p1.y * aw[5]  + p1.z * aw[6]  + p1.w * aw[7];
    s += p2.x * aw[8]  + p2.y * aw[9]  + p2.z * aw[10] + p2.w * aw[11];
    s += p3.x * aw[12] + p3.y * aw[13] + p3.z * aw[14] + p3.w * aw[15];
    __stcs(out + (size_t)b * TNC + i, s);
}

// ---------------------------------------------------------------------------
extern "C" void kernel_launch(void* const* d_in, const int* in_sizes, int n_in,
                              void* d_out, int out_size) {
    const float *query = nullptr, *keys = nullptr, *V = nullptr,
                *W = nullptr, *bias = nullptr;
    for (int i = 0; i < n_in; i++) {
        switch (in_sizes[i]) {
            case Bn * DQ:            query = (const float*)d_in[i]; break;
            case Bn * DK * NK:       keys  = (const float*)d_in[i]; break;
            case Bn * TNC * NK:      V     = (const float*)d_in[i]; break;
            case Hn * DQ * DK:       W     = (const float*)d_in[i]; break;
            case Hn * DQ:            bias  = (const float*)d_in[i]; break;
            default: break;
        }
    }
    float* out = (float*)d_out;

    float* part; cudaGetSymbolAddress((void**)&part, g_part);
    float* att;  cudaGetSymbolAddress((void**)&att,  g_att);

    cudaFuncSetAttribute(gemm_att_pf,
                         cudaFuncAttributeMaxDynamicSharedMemorySize,
                         GEMM_SMEM_BYTES);

    gemm_att_pf<<<NGEMM + NPF, 256, GEMM_SMEM_BYTES>>>(keys, W, bias, query, V,
                                                       part, att);

    dim3 gridC(TNC / 256, Bn);              // (621, 32)
    weighted_v_kernel<<<gridC, 256>>>(V, att, out);
}

// round 11
// speedup vs baseline: 1.1635x; 1.1635x over previous
#include <cuda_runtime.h>
#include <cuda_bf16.h>
#include <math.h>
#include <stdint.h>

// Problem constants
#define Bn   32
#define DQ   512
#define DK   512
#define NK   16
#define Hn   8
#define Tt   12
#define Nn   207
#define Cc   64
#define TNC  (Tt*Nn*Cc)      // 158976
#define Mrows (Bn*NK)        // 512
#define Ncols (Hn*DQ)        // 4096
#define NXB  32              // col blocks (4096/128)

__device__ float g_part[NXB * Mrows];  // per-colblock logits partials
__device__ float g_att[Mrows];         // softmax weights

// ---------------------------------------------------------------------------
__device__ __forceinline__ void mma_tf32(float* c, const uint32_t* a,
                                         uint32_t b0, uint32_t b1) {
    asm volatile(
        "mma.sync.aligned.m16n8k8.row.col.f32.tf32.tf32.f32 "
        "{%0,%1,%2,%3}, {%4,%5,%6,%7}, {%8,%9}, {%0,%1,%2,%3};"
        : "+f"(c[0]), "+f"(c[1]), "+f"(c[2]), "+f"(c[3])
        : "r"(a[0]), "r"(a[1]), "r"(a[2]), "r"(a[3]), "r"(b0), "r"(b1));
}

__device__ __forceinline__ void cp_async16(uint32_t smem_addr, const void* gptr) {
    asm volatile("cp.async.cg.shared.global [%0], [%1], 16;"
                 :: "r"(smem_addr), "l"(gptr));
}

// ---------------------------------------------------------------------------
// Kernel A: tf32 GEMM (R5 structure) + register-fragment double buffering.
// BM=128, BN=128, BK=32; 256 threads (2x4 warps), warp tile 64x32; 2-stage
// cp.async; A direct from keys (fused transpose, XOR-swizzled).
// Mainloop pipelines fragment LDS of ks+1 under MMAs of ks.
// ---------------------------------------------------------------------------
#define SSTR 36
#define A_TILE_F 4096
#define B_TILE_F (128 * SSTR)
#define GEMM_SMEM_F (2*(A_TILE_F + B_TILE_F) + 8*128 + 128 + 128)
#define GEMM_SMEM_BYTES (GEMM_SMEM_F * 4)

__global__ __launch_bounds__(256, 1)
void gemm_att_tc(const float* __restrict__ keys, const float* __restrict__ W,
                 const float* __restrict__ bias, const float* __restrict__ query,
                 float* __restrict__ part) {
    extern __shared__ float smem[];
    float* As    = smem;                      // 2 * 4096 [bloc*512 + d*16 + k] swz
    float* Bs    = As + 2 * A_TILE_F;         // 2 * 4608 [n*36 + d]
    float* Qs    = Bs + 2 * B_TILE_F;         // 8*128
    float* biasS = Qs + 8 * 128;              // 128
    float* partS = biasS + 128;               // 128

    int tid  = threadIdx.x;
    int lane = tid & 31;
    int warp = tid >> 5;
    int warp_m = warp >> 2;        // 0..1
    int warp_n = warp & 3;         // 0..3
    int g   = lane >> 2;           // 0..7
    int tig = lane & 3;            // 0..3
    int swz = (tig & 2) << 2;

    int c0 = blockIdx.x * 128;
    int m0 = blockIdx.y * 128;
    int q0 = c0 & (DQ - 1);
    int b0 = m0 >> 4;              // 8 batches per 128 rows

    uint32_t sA = (uint32_t)__cvta_generic_to_shared(As);
    uint32_t sB = (uint32_t)__cvta_generic_to_shared(Bs);

    for (int i = tid; i < 8 * 128; i += 256)
        Qs[i] = query[(b0 + (i >> 7)) * DQ + q0 + (i & 127)];
    if (tid < 128) { biasS[tid] = bias[c0 + tid]; partS[tid] = 0.0f; }

    auto issue_tile = [&](int kt, int s) {
        uint32_t aBase = sA + (uint32_t)(s * A_TILE_F) * 4;
        uint32_t bBase = sB + (uint32_t)(s * B_TILE_F) * 4;
        #pragma unroll
        for (int i = 0; i < 4; i++) {
            int flat = i * 256 + tid;          // 0..1023
            int bloc = flat >> 7;              // 0..7
            int rem  = flat & 127;
            int dl   = rem >> 2;               // 0..31
            int kkc  = rem & 3;                // 0..3
            const float* src = keys + (size_t)(b0 + bloc) * (DK * NK)
                             + (size_t)(kt + dl) * NK + kkc * 4;
            int woff = bloc * 512 + dl * 16 + ((kkc * 4) ^ ((dl & 2) << 2));
            cp_async16(aBase + (uint32_t)woff * 4, src);
        }
        #pragma unroll
        for (int i = 0; i < 4; i++) {
            int flat = i * 256 + tid;
            int r = flat >> 3, cc = flat & 7;
            const float* src = W + (size_t)(c0 + r) * DK + kt + cc * 4;
            cp_async16(bBase + (uint32_t)(r * SSTR + cc * 4) * 4, src);
        }
        asm volatile("cp.async.commit_group;");
    };

    float acc[4][4][4] = {};
    uint32_t aF[2][4][4], bF[2][4][2];

    issue_tile(0, 0);

    for (int it = 0; it < 16; it++) {
        int buf = it & 1;
        if (it < 15) {
            issue_tile((it + 1) * 32, buf ^ 1);
            asm volatile("cp.async.wait_group 1;");
        } else {
            asm volatile("cp.async.wait_group 0;");
        }
        __syncthreads();

        const float* Ab = As + buf * A_TILE_F;
        const float* Bb = Bs + buf * B_TILE_F;

        // fragment load for one ks into register buffer pb
        auto load_frags = [&](int ks, int pb) {
            int k = ks * 8 + tig;              // k&2 == tig&2 (swizzle invariant)
            #pragma unroll
            for (int mt = 0; mt < 4; mt++) {
                int bloc = warp_m * 4 + mt;
                const float* ab = &Ab[bloc * 512];
                aF[pb][mt][0] = __float_as_uint(ab[(k    ) * 16 + ( g      ^ swz)]);
                aF[pb][mt][1] = __float_as_uint(ab[(k    ) * 16 + ((g + 8) ^ swz)]);
                aF[pb][mt][2] = __float_as_uint(ab[(k + 4) * 16 + ( g      ^ swz)]);
                aF[pb][mt][3] = __float_as_uint(ab[(k + 4) * 16 + ((g + 8) ^ swz)]);
            }
            #pragma unroll
            for (int nt = 0; nt < 4; nt++) {
                int nbase = warp_n * 32 + nt * 8 + g;
                bF[pb][nt][0] = __float_as_uint(Bb[nbase * SSTR + k    ]);
                bF[pb][nt][1] = __float_as_uint(Bb[nbase * SSTR + k + 4]);
            }
        };

        load_frags(0, 0);                       // preload ks=0
        #pragma unroll
        for (int ks = 0; ks < 4; ks++) {
            int pb = ks & 1;
            if (ks < 3) load_frags(ks + 1, pb ^ 1);  // overlap with MMAs below
            #pragma unroll
            for (int nt = 0; nt < 4; nt++)
                #pragma unroll
                for (int mt = 0; mt < 4; mt++)
                    mma_tf32(acc[mt][nt], aF[pb][mt], bF[pb][nt][0], bF[pb][nt][1]);
        }
        __syncthreads();
    }

    // Epilogue: bias + relu + Q-weight, reduce per row
    #pragma unroll
    for (int mt = 0; mt < 4; mt++) {
        int mlo = warp_m * 64 + mt * 16 + g;
        int mhi = mlo + 8;
        const float* q_lo = &Qs[(mlo >> 4) * 128];
        const float* q_hi = &Qs[(mhi >> 4) * 128];
        float p_lo = 0.0f, p_hi = 0.0f;
        #pragma unroll
        for (int nt = 0; nt < 4; nt++) {
            int cl = warp_n * 32 + nt * 8 + 2 * tig;
            float bi0 = biasS[cl], bi1 = biasS[cl + 1];
            p_lo = fmaf(fmaxf(acc[mt][nt][0] + bi0, 0.0f), q_lo[cl],     p_lo);
            p_lo = fmaf(fmaxf(acc[mt][nt][1] + bi1, 0.0f), q_lo[cl + 1], p_lo);
            p_hi = fmaf(fmaxf(acc[mt][nt][2] + bi0, 0.0f), q_hi[cl],     p_hi);
            p_hi = fmaf(fmaxf(acc[mt][nt][3] + bi1, 0.0f), q_hi[cl + 1], p_hi);
        }
        p_lo += __shfl_xor_sync(0xffffffffu, p_lo, 1);
        p_lo += __shfl_xor_sync(0xffffffffu, p_lo, 2);
        p_hi += __shfl_xor_sync(0xffffffffu, p_hi, 1);
        p_hi += __shfl_xor_sync(0xffffffffu, p_hi, 2);
        if (tig == 0) {
            atomicAdd(&partS[mlo], p_lo);
            atomicAdd(&partS[mhi], p_hi);
        }
    }
    __syncthreads();
    if (tid < 128) part[blockIdx.x * Mrows + m0 + tid] = partS[tid];
}

// ---------------------------------------------------------------------------
// Kernel B: reduce per-colblock partials + softmax. One block per batch b.
// ---------------------------------------------------------------------------
__global__ __launch_bounds__(512)
void softmax_kernel(const float* __restrict__ part, float* __restrict__ att) {
    __shared__ float s[512];
    int b = blockIdx.x;
    int tid = threadIdx.x;
    int xblk = tid >> 4, k = tid & 15;
    s[tid] = part[xblk * Mrows + b * NK + k];
    __syncthreads();
    #pragma unroll
    for (int off = 256; off >= 16; off >>= 1) {
        if (tid < off) s[tid] += s[tid + off];
        __syncthreads();
    }
    if (tid < 32) {
        const float scale = 1.0f / (8.0f * 22.62741699796952f);  // 1/(H*sqrt(512))
        float v = (tid < NK) ? s[tid] * scale : -1e30f;
        float m = v;
        #pragma unroll
        for (int o = 8; o; o >>= 1) m = fmaxf(m, __shfl_xor_sync(0xffffffffu, m, o));
        float e = (tid < NK) ? __expf(v - m) : 0.0f;
        float z = e;
        #pragma unroll
        for (int o = 8; o; o >>= 1) z += __shfl_xor_sync(0xffffffffu, z, o);
        if (tid < NK) att[b * NK + tid] = e / z;
    }
}

// ---------------------------------------------------------------------------
// Kernel C: att-weighted V reduction — R1-proven body (best measured ~55us).
// ---------------------------------------------------------------------------
__global__ __launch_bounds__(256)
void weighted_v_kernel(const float* __restrict__ V, const float* __restrict__ att,
                       float* __restrict__ out) {
    __shared__ float aw[NK];
    int b = blockIdx.y;
    if (threadIdx.x < NK) aw[threadIdx.x] = att[b * NK + threadIdx.x];
    __syncthreads();
    int i = blockIdx.x * blockDim.x + threadIdx.x;
    if (i >= TNC) return;
    const float4* v4 = (const float4*)(V + ((size_t)b * TNC + i) * NK);
    float4 p0 = v4[0], p1 = v4[1], p2 = v4[2], p3 = v4[3];
    float s;
    s  = p0.x * aw[0]  + p0.y * aw[1]  + p0.z * aw[2]  + p0.w * aw[3];
    s += p1.x * aw[4]  + p1.y * aw[5]  + p1.z * aw[6]  + p1.w * aw[7];
    s += p2.x * aw[8]  + p2.y * aw[9]  + p2.z * aw[10] + p2.w * aw[11];
    s += p3.x * aw[12] + p3.y * aw[13] + p3.z * aw[14] + p3.w * aw[15];
    out[(size_t)b * TNC + i] = s;
}

// ---------------------------------------------------------------------------
extern "C" void kernel_launch(void* const* d_in, const int* in_sizes, int n_in,
                              void* d_out, int out_size) {
    const float *query = nullptr, *keys = nullptr, *V = nullptr,
                *W = nullptr, *bias = nullptr;
    for (int i = 0; i < n_in; i++) {
        switch (in_sizes[i]) {
            case Bn * DQ:            query = (const float*)d_in[i]; break;
            case Bn * DK * NK:       keys  = (const float*)d_in[i]; break;
            case Bn * TNC * NK:      V     = (const float*)d_in[i]; break;
            case Hn * DQ * DK:       W     = (const float*)d_in[i]; break;
            case Hn * DQ:            bias  = (const float*)d_in[i]; break;
            default: break;
        }
    }
    float* out = (float*)d_out;

    float* part; cudaGetSymbolAddress((void**)&part, g_part);
    float* att;  cudaGetSymbolAddress((void**)&att,  g_att);

    cudaFuncSetAttribute(gemm_att_tc,
                         cudaFuncAttributeMaxDynamicSharedMemorySize,
                         GEMM_SMEM_BYTES);

    dim3 gridA(NXB, Mrows / 128);           // (32, 4) = 128 blocks
    gemm_att_tc<<<gridA, 256, GEMM_SMEM_BYTES>>>(keys, W, bias, query, part);

    softmax_kernel<<<Bn, 512>>>(part, att);

    dim3 gridC(TNC / 256, Bn);              // (621, 32)
    weighted_v_kernel<<<gridC, 256>>>(V, att, out);
}